// round 3
// baseline (speedup 1.0000x reference)
#include <cuda_runtime.h>

#define Mv    32768
#define Ev    262144
#define RANKv 5
#define FILTv 32
#define FINv  32
#define NBv   8
#define VEC   256   // FIN * NB

typedef unsigned long long u64;

struct alignas(8) Edge { int c; float w; };

__device__ float g_Ta[(size_t)Mv * VEC];
__device__ float g_Tb[(size_t)Mv * VEC];
__device__ float g_Tc[(size_t)Mv * VEC];
__device__ int   g_cnt[Mv];
__device__ int   g_rowptr[Mv + 1];
__device__ int   g_pos[Ev];
__device__ Edge  g_edge[Ev];

// ---- packed f32x2 helpers ----
__device__ __forceinline__ u64 f2_pack(float lo, float hi) {
    u64 d; asm("mov.b64 %0, {%1, %2};" : "=l"(d) : "f"(lo), "f"(hi)); return d;
}
__device__ __forceinline__ void f2_unpack(u64 v, float& lo, float& hi) {
    asm("mov.b64 {%0, %1}, %2;" : "=f"(lo), "=f"(hi) : "l"(v));
}
__device__ __forceinline__ u64 f2_fma(u64 a, u64 b, u64 c) {
    u64 d; asm("fma.rn.f32x2 %0, %1, %2, %3;" : "=l"(d) : "l"(a), "l"(b), "l"(c)); return d;
}

// ---------------- CSR build ----------------
__global__ void k_zero() { g_cnt[blockIdx.x * 256 + threadIdx.x] = 0; }

__global__ void k_hist(const int* __restrict__ rows) {
    int e = blockIdx.x * 256 + threadIdx.x;
    g_pos[e] = atomicAdd(&g_cnt[rows[e]], 1);
}

__global__ void k_scan() {
    __shared__ int part[1024];
    int t = threadIdx.x;
    int base = t * 32;
    int s = 0;
#pragma unroll
    for (int i = 0; i < 32; i++) s += g_cnt[base + i];
    part[t] = s;
    __syncthreads();
    for (int off = 1; off < 1024; off <<= 1) {
        int v = (t >= off) ? part[t - off] : 0;
        __syncthreads();
        part[t] += v;
        __syncthreads();
    }
    int excl = (t == 0) ? 0 : part[t - 1];
#pragma unroll
    for (int i = 0; i < 32; i++) {
        g_rowptr[base + i] = excl;
        excl += g_cnt[base + i];
    }
    if (t == 1023) g_rowptr[Mv] = Ev;
}

__global__ void k_scatter(const int* __restrict__ rows,
                          const int* __restrict__ cols,
                          const float* __restrict__ vals) {
    int e = blockIdx.x * 256 + threadIdx.x;
    int idx = g_rowptr[rows[e]] + g_pos[e];
    Edge ed; ed.c = cols[e] * VEC; ed.w = vals[e];
    g_edge[idx] = ed;
}

// ---------------- shared GEMM epilogue ----------------
__device__ __forceinline__ void gemm_epilogue(const float shv_r[VEC],
                                              const float* __restrict__ shW,
                                              int n, int fb,
                                              u64& a01, u64& a23) {
#pragma unroll
    for (int f = 0; f < FINv; f++) {
        float s = shv_r[f * NBv + n];
        u64 sd = f2_pack(s, s);
        float4 wv = *(const float4*)&shW[f * FILTv + fb];
        a01 = f2_fma(sd, f2_pack(wv.x, wv.y), a01);
        a23 = f2_fma(sd, f2_pack(wv.z, wv.w), a23);
    }
}

// ---------------- init: T0 + k=0 contribution + bias ----------------
__global__ void __launch_bounds__(256) k_init(const float* __restrict__ x,
                                              const float* __restrict__ kern,
                                              const float* __restrict__ bias,
                                              float* __restrict__ out) {
    __shared__ float shv[4][VEC];
    __shared__ float shW[FINv * FILTv];
    int t = threadIdx.x;
    int m0 = blockIdx.x * 4;
    int n8 = t >> 5, f = t & 31;
#pragma unroll
    for (int r = 0; r < 4; r++)
        shv[r][f * NBv + n8] = x[((size_t)n8 * Mv + (m0 + r)) * FINv + f];
    for (int i = t; i < FINv * FILTv; i += 256) {
        int ff = i >> 5, fl = i & 31;
        shW[i] = kern[(ff * RANKv + 0) * FILTv + fl];
    }
    __syncthreads();

    int r = t >> 6, l = t & 63;
    int m = m0 + r;
    *(float4*)&g_Ta[(size_t)m * VEC + 4 * l] = *(const float4*)&shv[r][4 * l];

    int n = l >> 3, fb = (l & 7) * 4;
    float4 bv = *(const float4*)&bias[fb];
    u64 a01 = f2_pack(bv.x, bv.y), a23 = f2_pack(bv.z, bv.w);
    gemm_epilogue(shv[r], shW, n, fb, a01, a23);
    float4 o;
    f2_unpack(a01, o.x, o.y);
    f2_unpack(a23, o.z, o.w);
    *(float4*)&out[((size_t)n * Mv + m) * FILTv + fb] = o;
}

// ---------------- fused Chebyshev step ----------------
__global__ void __launch_bounds__(256) k_step(int prevIdx, int ppIdx, int curIdx,
                                              const float* __restrict__ kern,
                                              float* __restrict__ out,
                                              int kidx, int isFirst, int writeT) {
    __shared__ float shv[4][VEC];
    __shared__ float shW[FINv * FILTv];

    float* bufs[3] = { g_Ta, g_Tb, g_Tc };
    const float* __restrict__ Tprev = bufs[prevIdx];
    const float* __restrict__ Tpp   = bufs[ppIdx];
    float* __restrict__ Tcur        = bufs[curIdx];

    int t = threadIdx.x;
    int r = t >> 6, l = t & 63;
    int m = blockIdx.x * 4 + r;
    int n = l >> 3, fb = (l & 7) * 4;

    // hoisted long-latency reads: overlap with gather loop
    size_t oi = ((size_t)n * Mv + m) * FILTv + fb;
    float4 ov = *(const float4*)&out[oi];              // out RMW read
    float4 pp = make_float4(0.f, 0.f, 0.f, 0.f);
    if (!isFirst) pp = *(const float4*)&Tpp[(size_t)m * VEC + 4 * l];

    for (int i = t; i < FINv * FILTv; i += 256) {
        int ff = i >> 5, fl = i & 31;
        shW[i] = kern[(ff * RANKv + kidx) * FILTv + fl];
    }

    int start = __ldg(&g_rowptr[m]), end = __ldg(&g_rowptr[m + 1]);
    u64 a0 = 0, a1 = 0, b0 = 0, b1 = 0;
    int e = start;
    // 4-deep software pipeline: all loads issued before FMAs
    for (; e + 4 <= end; e += 4) {
        Edge e0 = g_edge[e + 0];
        Edge e1 = g_edge[e + 1];
        Edge e2 = g_edge[e + 2];
        Edge e3 = g_edge[e + 3];
        float4 v0 = *(const float4*)&Tprev[(size_t)e0.c + 4 * l];
        float4 v1 = *(const float4*)&Tprev[(size_t)e1.c + 4 * l];
        float4 v2 = *(const float4*)&Tprev[(size_t)e2.c + 4 * l];
        float4 v3 = *(const float4*)&Tprev[(size_t)e3.c + 4 * l];
        u64 w0 = f2_pack(e0.w, e0.w), w1 = f2_pack(e1.w, e1.w);
        u64 w2 = f2_pack(e2.w, e2.w), w3 = f2_pack(e3.w, e3.w);
        a0 = f2_fma(w0, f2_pack(v0.x, v0.y), a0);
        a1 = f2_fma(w0, f2_pack(v0.z, v0.w), a1);
        b0 = f2_fma(w1, f2_pack(v1.x, v1.y), b0);
        b1 = f2_fma(w1, f2_pack(v1.z, v1.w), b1);
        a0 = f2_fma(w2, f2_pack(v2.x, v2.y), a0);
        a1 = f2_fma(w2, f2_pack(v2.z, v2.w), a1);
        b0 = f2_fma(w3, f2_pack(v3.x, v3.y), b0);
        b1 = f2_fma(w3, f2_pack(v3.z, v3.w), b1);
    }
    for (; e < end; e++) {
        Edge ed = g_edge[e];
        float4 v = *(const float4*)&Tprev[(size_t)ed.c + 4 * l];
        u64 wd = f2_pack(ed.w, ed.w);
        a0 = f2_fma(wd, f2_pack(v.x, v.y), a0);
        a1 = f2_fma(wd, f2_pack(v.z, v.w), a1);
    }

    float ax, ay, az, aw, bx, by, bz, bw;
    f2_unpack(a0, ax, ay); f2_unpack(a1, az, aw);
    f2_unpack(b0, bx, by); f2_unpack(b1, bz, bw);
    float4 val = make_float4(ax + bx, ay + by, az + bz, aw + bw);
    if (!isFirst) {
        val.x = 2.f * val.x - pp.x;
        val.y = 2.f * val.y - pp.y;
        val.z = 2.f * val.z - pp.z;
        val.w = 2.f * val.w - pp.w;
    }
    if (writeT)
        *(float4*)&Tcur[(size_t)m * VEC + 4 * l] = val;

    *(float4*)&shv[r][4 * l] = val;
    __syncthreads();

    u64 a01 = f2_pack(ov.x, ov.y), a23 = f2_pack(ov.z, ov.w);
    gemm_epilogue(shv[r], shW, n, fb, a01, a23);
    float4 o;
    f2_unpack(a01, o.x, o.y);
    f2_unpack(a23, o.z, o.w);
    *(float4*)&out[oi] = o;
}

extern "C" void kernel_launch(void* const* d_in, const int* in_sizes, int n_in,
                              void* d_out, int out_size) {
    const float* x    = (const float*)d_in[0];
    const float* vals = (const float*)d_in[1];
    const float* kern = (const float*)d_in[2];
    const float* bias = (const float*)d_in[3];
    const int*   rows = (const int*)  d_in[4];
    const int*   cols = (const int*)  d_in[5];
    float* out = (float*)d_out;

    k_zero   <<<Mv / 256, 256>>>();
    k_hist   <<<Ev / 256, 256>>>(rows);
    k_scan   <<<1, 1024>>>();
    k_scatter<<<Ev / 256, 256>>>(rows, cols, vals);

    k_init<<<Mv / 4, 256>>>(x, kern, bias, out);

    k_step<<<Mv / 4, 256>>>(0, 0, 1, kern, out, 1, 1, 1);  // T1 = L T0       (Ta -> Tb)
    k_step<<<Mv / 4, 256>>>(1, 0, 2, kern, out, 2, 0, 1);  // T2 = 2L T1 - T0 (-> Tc)
    k_step<<<Mv / 4, 256>>>(2, 1, 0, kern, out, 3, 0, 1);  // T3              (-> Ta)
    k_step<<<Mv / 4, 256>>>(0, 2, 1, kern, out, 4, 0, 0);  // T4 (no store)
}

// round 4
// speedup vs baseline: 1.0963x; 1.0963x over previous
#include <cuda_runtime.h>
#include <cuda_fp16.h>

#define Mv    32768
#define Ev    262144
#define RANKv 5
#define FILTv 32
#define FINv  32
#define NBv   8
#define VEC   256   // FIN * NB

typedef unsigned long long u64;
typedef unsigned int u32;

struct alignas(8) Edge { int c; float w; };

// T terms, fp16: 5 x 16.75MB
__device__ __half g_T[RANKv][(size_t)Mv * VEC];
__device__ int   g_cnt[Mv];
__device__ int   g_rowptr[Mv + 1];
__device__ int   g_pos[Ev];
__device__ Edge  g_edge[Ev];

__device__ __forceinline__ u64 f2_pack(float lo, float hi) {
    u64 d; asm("mov.b64 %0, {%1, %2};" : "=l"(d) : "f"(lo), "f"(hi)); return d;
}
__device__ __forceinline__ void f2_unpack(u64 v, float& lo, float& hi) {
    asm("mov.b64 {%0, %1}, %2;" : "=f"(lo), "=f"(hi) : "l"(v));
}
__device__ __forceinline__ u64 f2_fma(u64 a, u64 b, u64 c) {
    u64 d; asm("fma.rn.f32x2 %0, %1, %2, %3;" : "=l"(d) : "l"(a), "l"(b), "l"(c)); return d;
}

// ---------------- CSR build ----------------
__global__ void k_zero() { g_cnt[blockIdx.x * 256 + threadIdx.x] = 0; }

__global__ void k_hist(const int* __restrict__ rows) {
    int e = blockIdx.x * 256 + threadIdx.x;
    g_pos[e] = atomicAdd(&g_cnt[rows[e]], 1);
}

__global__ void k_scan() {
    __shared__ int part[1024];
    int t = threadIdx.x;
    int base = t * 32;
    int s = 0;
#pragma unroll
    for (int i = 0; i < 32; i++) s += g_cnt[base + i];
    part[t] = s;
    __syncthreads();
    for (int off = 1; off < 1024; off <<= 1) {
        int v = (t >= off) ? part[t - off] : 0;
        __syncthreads();
        part[t] += v;
        __syncthreads();
    }
    int excl = (t == 0) ? 0 : part[t - 1];
#pragma unroll
    for (int i = 0; i < 32; i++) {
        g_rowptr[base + i] = excl;
        excl += g_cnt[base + i];
    }
    if (t == 1023) g_rowptr[Mv] = Ev;
}

__global__ void k_scatter(const int* __restrict__ rows,
                          const int* __restrict__ cols,
                          const float* __restrict__ vals) {
    int e = blockIdx.x * 256 + threadIdx.x;
    int idx = g_rowptr[rows[e]] + g_pos[e];
    Edge ed; ed.c = cols[e] * VEC; ed.w = vals[e];
    g_edge[idx] = ed;
}

// ---------------- init: x[NB,M,FIN] fp32 -> T0[m][f*8+n] fp16 ----------------
__global__ void __launch_bounds__(256) k_init(const float* __restrict__ x) {
    int t = threadIdx.x;
    int mr = t >> 5, f = t & 31;
    int m = blockIdx.x * 8 + mr;
    float v[8];
#pragma unroll
    for (int n = 0; n < 8; n++)
        v[n] = x[((size_t)n * Mv + m) * FINv + f];
    uint4 u;
    __half2 h;
    h = __floats2half2_rn(v[0], v[1]); u.x = *(u32*)&h;
    h = __floats2half2_rn(v[2], v[3]); u.y = *(u32*)&h;
    h = __floats2half2_rn(v[4], v[5]); u.z = *(u32*)&h;
    h = __floats2half2_rn(v[6], v[7]); u.w = *(u32*)&h;
    *(uint4*)&g_T[0][(size_t)m * VEC + 8 * f] = u;
}

// ---------------- Chebyshev step: one warp per row, fp16 in/out, fp32 accum ----------------
__global__ void __launch_bounds__(256) k_step(int prevIdx, int ppIdx, int curIdx, int isFirst) {
    int t = threadIdx.x;
    int w = t >> 5, l = t & 31;
    int m = blockIdx.x * 8 + w;

    const __half* __restrict__ Tprev = g_T[prevIdx];
    const __half* __restrict__ Tpp   = g_T[ppIdx];
    __half* __restrict__ Tcur        = g_T[curIdx];

    size_t base = (size_t)m * VEC + 8 * l;
    uint4 ppu = make_uint4(0, 0, 0, 0);
    if (!isFirst) ppu = *(const uint4*)&Tpp[base];   // hoisted

    int s = __ldg(&g_rowptr[m]), e = __ldg(&g_rowptr[m + 1]);
    float2 a0 = {0.f,0.f}, a1 = {0.f,0.f}, a2 = {0.f,0.f}, a3 = {0.f,0.f};
    for (int i = s; i < e; i++) {
        Edge ed = g_edge[i];
        uint4 v = *(const uint4*)&Tprev[(size_t)ed.c + 8 * l];
        float wv = ed.w;
        float2 f0 = __half22float2(*(__half2*)&v.x);
        float2 f1 = __half22float2(*(__half2*)&v.y);
        float2 f2v = __half22float2(*(__half2*)&v.z);
        float2 f3 = __half22float2(*(__half2*)&v.w);
        a0.x += wv * f0.x;  a0.y += wv * f0.y;
        a1.x += wv * f1.x;  a1.y += wv * f1.y;
        a2.x += wv * f2v.x; a2.y += wv * f2v.y;
        a3.x += wv * f3.x;  a3.y += wv * f3.y;
    }

    if (!isFirst) {
        float2 p0 = __half22float2(*(__half2*)&ppu.x);
        float2 p1 = __half22float2(*(__half2*)&ppu.y);
        float2 p2 = __half22float2(*(__half2*)&ppu.z);
        float2 p3 = __half22float2(*(__half2*)&ppu.w);
        a0.x = 2.f * a0.x - p0.x;  a0.y = 2.f * a0.y - p0.y;
        a1.x = 2.f * a1.x - p1.x;  a1.y = 2.f * a1.y - p1.y;
        a2.x = 2.f * a2.x - p2.x;  a2.y = 2.f * a2.y - p2.y;
        a3.x = 2.f * a3.x - p3.x;  a3.y = 2.f * a3.y - p3.y;
    }

    uint4 u;
    __half2 h;
    h = __floats2half2_rn(a0.x, a0.y); u.x = *(u32*)&h;
    h = __floats2half2_rn(a1.x, a1.y); u.y = *(u32*)&h;
    h = __floats2half2_rn(a2.x, a2.y); u.z = *(u32*)&h;
    h = __floats2half2_rn(a3.x, a3.y); u.w = *(u32*)&h;
    *(uint4*)&Tcur[base] = u;
}

// ---------------- final GEMM: out[n][m][filt] = bias + sum_{f,k} T_k[m,f,n] W[f*5+k][filt] ----------------
#define ROWS_PB 16
#define ROWPAD  (RANKv * VEC + 8)   // 1288 floats, stride % 32 == 8 -> conflict-free across rows

__global__ void __launch_bounds__(128) k_fin(const float* __restrict__ kern,
                                             const float* __restrict__ bias,
                                             float* __restrict__ out) {
    extern __shared__ float sm[];
    float* sT = sm;                          // [16][1288]
    float* sW = sm + ROWS_PB * ROWPAD;       // [160*32]

    int t = threadIdx.x;
    int m0 = blockIdx.x * ROWS_PB;

    // load W (5120 floats = 1280 float4)
    for (int i = t; i < (RANKv * FINv * FILTv) / 4; i += 128)
        ((float4*)sW)[i] = ((const float4*)kern)[i];

    // load + convert T: 4 warps, warp w -> rows 4w..4w+3
    {
        int w = t >> 5, l = t & 31;
#pragma unroll
        for (int rr = 0; rr < 4; rr++) {
            int r = w * 4 + rr;
            int m = m0 + r;
#pragma unroll
            for (int k = 0; k < RANKv; k++) {
                uint4 v = *(const uint4*)&g_T[k][(size_t)m * VEC + 8 * l];
                float2 f0 = __half22float2(*(__half2*)&v.x);
                float2 f1 = __half22float2(*(__half2*)&v.y);
                float2 f2v = __half22float2(*(__half2*)&v.z);
                float2 f3 = __half22float2(*(__half2*)&v.w);
                float* dst = &sT[r * ROWPAD + k * VEC + l];   // [n*32+l]
                dst[0*32] = f0.x; dst[1*32] = f0.y;
                dst[2*32] = f1.x; dst[3*32] = f1.y;
                dst[4*32] = f2v.x; dst[5*32] = f2v.y;
                dst[6*32] = f3.x;  dst[7*32] = f3.y;
            }
        }
    }
    __syncthreads();

    // compute: thread -> (r, n2, j4): 4 n x 8 filt = 32 outputs
    int r  = t >> 3;
    int n2 = (t >> 2) & 1;     // n = n2*4 + i
    int j4 = t & 3;            // filts j4*8 .. +7
    int m  = m0 + r;

    u64 acc[4][4];
    {
        float4 b0 = *(const float4*)&bias[j4 * 8];
        float4 b1 = *(const float4*)&bias[j4 * 8 + 4];
        u64 bp0 = f2_pack(b0.x, b0.y), bp1 = f2_pack(b0.z, b0.w);
        u64 bp2 = f2_pack(b1.x, b1.y), bp3 = f2_pack(b1.z, b1.w);
#pragma unroll
        for (int i = 0; i < 4; i++) {
            acc[i][0] = bp0; acc[i][1] = bp1; acc[i][2] = bp2; acc[i][3] = bp3;
        }
    }

    const float* sTr = &sT[r * ROWPAD];
#pragma unroll 1
    for (int f = 0; f < FINv; f++) {
#pragma unroll
        for (int k = 0; k < RANKv; k++) {
            int col = f * RANKv + k;
            float4 w0 = *(const float4*)&sW[col * FILTv + j4 * 8];
            float4 w1 = *(const float4*)&sW[col * FILTv + j4 * 8 + 4];
            u64 wp0, wp1, wp2, wp3;
            wp0 = f2_pack(w0.x, w0.y); wp1 = f2_pack(w0.z, w0.w);
            wp2 = f2_pack(w1.x, w1.y); wp3 = f2_pack(w1.z, w1.w);
#pragma unroll
            for (int i = 0; i < 4; i++) {
                float s = sTr[k * VEC + (n2 * 4 + i) * 32 + f];
                u64 sp = f2_pack(s, s);
                acc[i][0] = f2_fma(sp, wp0, acc[i][0]);
                acc[i][1] = f2_fma(sp, wp1, acc[i][1]);
                acc[i][2] = f2_fma(sp, wp2, acc[i][2]);
                acc[i][3] = f2_fma(sp, wp3, acc[i][3]);
            }
        }
    }

#pragma unroll
    for (int i = 0; i < 4; i++) {
        int n = n2 * 4 + i;
        size_t oi = ((size_t)n * Mv + m) * FILTv + j4 * 8;
        float4 o0, o1;
        f2_unpack(acc[i][0], o0.x, o0.y); f2_unpack(acc[i][1], o0.z, o0.w);
        f2_unpack(acc[i][2], o1.x, o1.y); f2_unpack(acc[i][3], o1.z, o1.w);
        *(float4*)&out[oi]     = o0;
        *(float4*)&out[oi + 4] = o1;
    }
}

extern "C" void kernel_launch(void* const* d_in, const int* in_sizes, int n_in,
                              void* d_out, int out_size) {
    const float* x    = (const float*)d_in[0];
    const float* vals = (const float*)d_in[1];
    const float* kern = (const float*)d_in[2];
    const float* bias = (const float*)d_in[3];
    const int*   rows = (const int*)  d_in[4];
    const int*   cols = (const int*)  d_in[5];
    float* out = (float*)d_out;

    static int smem_set = 0;
    int fin_smem = (ROWS_PB * ROWPAD + RANKv * FINv * FILTv) * 4;
    if (!smem_set) {
        cudaFuncSetAttribute(k_fin, cudaFuncAttributeMaxDynamicSharedMemorySize, fin_smem);
        smem_set = 1;
    }

    k_zero   <<<Mv / 256, 256>>>();
    k_hist   <<<Ev / 256, 256>>>(rows);
    k_scan   <<<1, 1024>>>();
    k_scatter<<<Ev / 256, 256>>>(rows, cols, vals);

    k_init<<<Mv / 8, 256>>>(x);

    k_step<<<Mv / 8, 256>>>(0, 0, 1, 1);   // T1 = L T0
    k_step<<<Mv / 8, 256>>>(1, 0, 2, 0);   // T2 = 2 L T1 - T0
    k_step<<<Mv / 8, 256>>>(2, 1, 3, 0);   // T3
    k_step<<<Mv / 8, 256>>>(3, 2, 4, 0);   // T4

    k_fin<<<Mv / ROWS_PB, 128, fin_smem>>>(kern, bias, out);
}

// round 5
// speedup vs baseline: 1.8644x; 1.7006x over previous
#include <cuda_runtime.h>
#include <cuda_fp16.h>
#include <mma.h>

using namespace nvcuda;

#define Mv    32768
#define Ev    262144
#define RANKv 5
#define FILTv 32
#define FINv  32
#define NBv   8
#define VEC   256   // FIN * NB

typedef unsigned long long u64;
typedef unsigned int u32;

struct alignas(8) Edge { int c; float w; };

// T terms, fp16, element layout per vertex: idx = n*32 + f
__device__ __half g_T[RANKv][(size_t)Mv * VEC];
__device__ int   g_cnt[Mv];          // zero at module load; re-zeroed by k_scan each replay
__device__ int   g_rowptr[Mv + 1];
__device__ int   g_pos[Ev];
__device__ Edge  g_edge[Ev];

// ---------------- CSR build ----------------
__global__ void k_hist(const int* __restrict__ rows) {
    int e = blockIdx.x * 256 + threadIdx.x;
    g_pos[e] = atomicAdd(&g_cnt[rows[e]], 1);
}

// scan g_cnt -> g_rowptr, then zero g_cnt (restores invariant for next replay)
__global__ void k_scan() {
    __shared__ int part[1024];
    int t = threadIdx.x;
    int base = t * 32;
    int s = 0;
#pragma unroll
    for (int i = 0; i < 32; i++) s += g_cnt[base + i];
    part[t] = s;
    __syncthreads();
    for (int off = 1; off < 1024; off <<= 1) {
        int v = (t >= off) ? part[t - off] : 0;
        __syncthreads();
        part[t] += v;
        __syncthreads();
    }
    int excl = (t == 0) ? 0 : part[t - 1];
#pragma unroll
    for (int i = 0; i < 32; i++) {
        g_rowptr[base + i] = excl;
        excl += g_cnt[base + i];
    }
    if (t == 1023) g_rowptr[Mv] = Ev;
#pragma unroll
    for (int i = 0; i < 32; i++) g_cnt[base + i] = 0;
}

// fused: blocks [0,1024) build edge array; blocks [1024,5120) transpose x -> T0 fp16
__global__ void __launch_bounds__(256) k_scatter_init(const int* __restrict__ rows,
                                                      const int* __restrict__ cols,
                                                      const float* __restrict__ vals,
                                                      const float* __restrict__ x) {
    int t = threadIdx.x;
    if (blockIdx.x < 1024) {
        int e = blockIdx.x * 256 + t;
        int idx = g_rowptr[rows[e]] + g_pos[e];
        Edge ed; ed.c = cols[e] * VEC; ed.w = vals[e];
        g_edge[idx] = ed;
    } else {
        int b = blockIdx.x - 1024;
        int m = b * 8 + (t >> 5);
        int l = t & 31;
        int n = l >> 2;            // element block 8l..8l+7 = n*32 + f0..f0+7
        int f0 = 8 * (l & 3);
        const float* xp = &x[((size_t)n * Mv + m) * FINv + f0];
        float4 va = *(const float4*)xp;
        float4 vb = *(const float4*)(xp + 4);
        uint4 u;
        __half2 h;
        h = __floats2half2_rn(va.x, va.y); u.x = *(u32*)&h;
        h = __floats2half2_rn(va.z, va.w); u.y = *(u32*)&h;
        h = __floats2half2_rn(vb.x, vb.y); u.z = *(u32*)&h;
        h = __floats2half2_rn(vb.z, vb.w); u.w = *(u32*)&h;
        *(uint4*)&g_T[0][(size_t)m * VEC + 8 * l] = u;
    }
}

// ---------------- Chebyshev step: one warp per row, fp16 in/out, fp32 accum ----------------
__global__ void __launch_bounds__(256) k_step(int prevIdx, int ppIdx, int curIdx, int isFirst) {
    int t = threadIdx.x;
    int w = t >> 5, l = t & 31;
    int m = blockIdx.x * 8 + w;

    const __half* __restrict__ Tprev = g_T[prevIdx];
    const __half* __restrict__ Tpp   = g_T[ppIdx];
    __half* __restrict__ Tcur        = g_T[curIdx];

    size_t base = (size_t)m * VEC + 8 * l;
    uint4 ppu = make_uint4(0, 0, 0, 0);
    if (!isFirst) ppu = *(const uint4*)&Tpp[base];

    int s = __ldg(&g_rowptr[m]), e = __ldg(&g_rowptr[m + 1]);
    float2 a0 = {0.f,0.f}, a1 = {0.f,0.f}, a2 = {0.f,0.f}, a3 = {0.f,0.f};
    for (int i = s; i < e; i++) {
        Edge ed = g_edge[i];
        uint4 v = *(const uint4*)&Tprev[(size_t)ed.c + 8 * l];
        float wv = ed.w;
        float2 f0 = __half22float2(*(__half2*)&v.x);
        float2 f1 = __half22float2(*(__half2*)&v.y);
        float2 f2v = __half22float2(*(__half2*)&v.z);
        float2 f3 = __half22float2(*(__half2*)&v.w);
        a0.x += wv * f0.x;  a0.y += wv * f0.y;
        a1.x += wv * f1.x;  a1.y += wv * f1.y;
        a2.x += wv * f2v.x; a2.y += wv * f2v.y;
        a3.x += wv * f3.x;  a3.y += wv * f3.y;
    }

    if (!isFirst) {
        float2 p0 = __half22float2(*(__half2*)&ppu.x);
        float2 p1 = __half22float2(*(__half2*)&ppu.y);
        float2 p2 = __half22float2(*(__half2*)&ppu.z);
        float2 p3 = __half22float2(*(__half2*)&ppu.w);
        a0.x = 2.f * a0.x - p0.x;  a0.y = 2.f * a0.y - p0.y;
        a1.x = 2.f * a1.x - p1.x;  a1.y = 2.f * a1.y - p1.y;
        a2.x = 2.f * a2.x - p2.x;  a2.y = 2.f * a2.y - p2.y;
        a3.x = 2.f * a3.x - p3.x;  a3.y = 2.f * a3.y - p3.y;
    }

    uint4 u;
    __half2 h;
    h = __floats2half2_rn(a0.x, a0.y); u.x = *(u32*)&h;
    h = __floats2half2_rn(a1.x, a1.y); u.y = *(u32*)&h;
    h = __floats2half2_rn(a2.x, a2.y); u.z = *(u32*)&h;
    h = __floats2half2_rn(a3.x, a3.y); u.w = *(u32*)&h;
    *(uint4*)&Tcur[base] = u;
}

// ---------------- final GEMM via tensor cores ----------------
// out[(n*Mv+m)*32+filt] = bias[filt] + sum_{kr,f} A[(n,m)][kr*32+f] * B[kr*32+f][filt]
//   A[(n,m)][kr*32+f] = g_T[kr][m*256 + n*32 + f]   (fp16, coalesced)
//   B[kr*32+f][filt]  = kern[(f*5+kr)*32 + filt]    (converted to fp16 in smem)
#define A_LD 168   // 160 + 8 halfs pad (336B rows, 16B multiple)

__global__ void __launch_bounds__(128) k_fin(const float* __restrict__ kern,
                                             const float* __restrict__ bias,
                                             float* __restrict__ out) {
    __shared__ __half smA[64 * A_LD];
    __shared__ __half smB[160 * FILTv];
    __shared__ float  smC[64 * FILTv];

    int t = threadIdx.x;
    int w = t >> 5, l = t & 31;
    int m0 = blockIdx.x * 8;

    // B: convert W fp32 -> fp16, reordered rows (kr*32+f)
    for (int i = t; i < 160 * FILTv; i += 128) {
        int row = i >> 5, filt = i & 31;
        int kr = row >> 5, f = row & 31;
        smB[i] = __float2half_rn(kern[(f * RANKv + kr) * FILTv + filt]);
    }

    // A: 64 rows (tr = n*8 + m_local) x 160 cols. Warp w loads m_local = 2w, 2w+1.
#pragma unroll
    for (int mm = 0; mm < 2; mm++) {
        int m_local = 2 * w + mm;
        int n = l >> 2, f0 = 8 * (l & 3);   // element block 8l within the 256-vector
#pragma unroll
        for (int kr = 0; kr < RANKv; kr++) {
            uint4 v = *(const uint4*)&g_T[kr][(size_t)(m0 + m_local) * VEC + 8 * l];
            int tr = n * 8 + m_local;
            *(uint4*)&smA[tr * A_LD + kr * 32 + f0] = v;
        }
    }
    __syncthreads();

    // compute: warp w -> row-tile [16w,16w+16), both 16-col tiles, 10 k-steps
    wmma::fragment<wmma::accumulator, 16, 16, 16, float> acc0, acc1;
    wmma::fill_fragment(acc0, 0.0f);
    wmma::fill_fragment(acc1, 0.0f);
#pragma unroll
    for (int kk = 0; kk < 10; kk++) {
        wmma::fragment<wmma::matrix_a, 16, 16, 16, __half, wmma::row_major> fa;
        wmma::fragment<wmma::matrix_b, 16, 16, 16, __half, wmma::row_major> fb0, fb1;
        wmma::load_matrix_sync(fa, &smA[16 * w * A_LD + kk * 16], A_LD);
        wmma::load_matrix_sync(fb0, &smB[kk * 16 * FILTv], FILTv);
        wmma::load_matrix_sync(fb1, &smB[kk * 16 * FILTv + 16], FILTv);
        wmma::mma_sync(acc0, fa, fb0, acc0);
        wmma::mma_sync(acc1, fa, fb1, acc1);
    }
    wmma::store_matrix_sync(&smC[16 * w * FILTv], acc0, FILTv, wmma::mem_row_major);
    wmma::store_matrix_sync(&smC[16 * w * FILTv + 16], acc1, FILTv, wmma::mem_row_major);
    __syncthreads();

    // write out with bias; rows tr = n*8+m_local -> out[(n*Mv + m0+m_local)*32 + filt]
    for (int i = t; i < 64 * FILTv; i += 128) {
        int tr = i >> 5, filt = i & 31;
        int n = tr >> 3, m_local = tr & 7;
        out[((size_t)n * Mv + m0 + m_local) * FILTv + filt] = smC[i] + bias[filt];
    }
}

extern "C" void kernel_launch(void* const* d_in, const int* in_sizes, int n_in,
                              void* d_out, int out_size) {
    const float* x    = (const float*)d_in[0];
    const float* vals = (const float*)d_in[1];
    const float* kern = (const float*)d_in[2];
    const float* bias = (const float*)d_in[3];
    const int*   rows = (const int*)  d_in[4];
    const int*   cols = (const int*)  d_in[5];
    float* out = (float*)d_out;

    k_hist        <<<Ev / 256, 256>>>(rows);                 // launch 1
    k_scan        <<<1, 1024>>>();                           // launch 2 (+ re-zero g_cnt)
    k_scatter_init<<<1024 + Mv / 8, 256>>>(rows, cols, vals, x); // launch 3
    k_step<<<Mv / 8, 256>>>(0, 0, 1, 1);   // launch 4  <- profiled slot
    k_step<<<Mv / 8, 256>>>(1, 0, 2, 0);
    k_step<<<Mv / 8, 256>>>(2, 1, 3, 0);
    k_step<<<Mv / 8, 256>>>(3, 2, 4, 0);
    k_fin<<<Mv / 8, 128>>>(kern, bias, out);
}